// round 9
// baseline (speedup 1.0000x reference)
#include <cuda_runtime.h>
#include <cuda_bf16.h>
#include <cstdint>
#include <cstring>
#include <math.h>

#define MAXS 24576

__device__ int   d_segstart[MAXS + 1];
__device__ float d_gsum[MAXS];
__device__ __nv_bfloat16 d_ph[(size_t)MAXS * 256];   // pooled hi (bf16 split)
__device__ __nv_bfloat16 d_pl[(size_t)MAXS * 256];   // pooled lo
__device__ __nv_bfloat16 d_Wth[256 * 256];           // Wm^T hi  [n][k]
__device__ __nv_bfloat16 d_Wtl[256 * 256];           // Wm^T lo

__device__ __forceinline__ float ex2f(float x) {
    float y; asm("ex2.approx.ftz.f32 %0, %1;" : "=f"(y) : "f"(x)); return y;
}
__device__ __forceinline__ float lg2f(float x) {
    float y; asm("lg2.approx.ftz.f32 %0, %1;" : "=f"(y) : "f"(x)); return y;
}
#define L2E 1.4426950408889634f

// ---------------------------------------------------------------------------
// Kernel 1: segment boundaries (index sorted), 4 nodes per thread.
// ---------------------------------------------------------------------------
__global__ void seg_bounds_kernel(const int* __restrict__ index, int N, int S) {
    int base = (blockIdx.x * blockDim.x + threadIdx.x) * 4;
    if (base >= N) return;
    int prev = (base == 0) ? -1 : index[base - 1];
    int v[4];
    if (base + 3 < N) {
        int4 q = *(const int4*)&index[base];
        v[0] = q.x; v[1] = q.y; v[2] = q.z; v[3] = q.w;
    } else {
        for (int k = 0; k < 4; k++) v[k] = (base + k < N) ? index[base + k] : 0;
    }
    #pragma unroll
    for (int k = 0; k < 4; k++) {
        int n = base + k;
        if (n < N) {
            for (int s = prev + 1; s <= v[k]; s++) d_segstart[s] = n;
            prev = v[k];
            if (n == N - 1)
                for (int s = v[k] + 1; s <= S; s++) d_segstart[s] = N;
        }
    }
}

// ---------------------------------------------------------------------------
// Kernel 2: prep — transpose + bf16-split Wm into Wt[n][k] (hi/lo).
// ---------------------------------------------------------------------------
__global__ void prep_kernel(const float* __restrict__ Wm) {
    __shared__ float tile[32][33];
    const int k0 = blockIdx.y * 32, n0 = blockIdx.x * 32;
    for (int r = threadIdx.y; r < 32; r += 8)
        tile[r][threadIdx.x] = Wm[(size_t)(k0 + r) * 256 + n0 + threadIdx.x];
    __syncthreads();
    for (int r = threadIdx.y; r < 32; r += 8) {
        float v = tile[threadIdx.x][r];
        __nv_bfloat16 h = __float2bfloat16(v);
        __nv_bfloat16 l = __float2bfloat16(v - __bfloat162float(h));
        size_t o = (size_t)(n0 + r) * 256 + k0 + threadIdx.x;
        d_Wth[o] = h;
        d_Wtl[o] = l;
    }
}

// ---------------------------------------------------------------------------
// Kernel 3: pooling — one warp per segment, online softmax, registers only.
// ---------------------------------------------------------------------------
__global__ __launch_bounds__(256) void pool_kernel(
    const float* __restrict__ x,
    const float* __restrict__ wts,
    const float* __restrict__ Wg,
    const float* __restrict__ bg,
    const float* __restrict__ p,
    int S)
{
    const int s = blockIdx.x * 8 + (threadIdx.x >> 5);
    if (s >= S) return;
    const int lane = threadIdx.x & 31;

    const float4* __restrict__ x4 = (const float4*)x;
    const float4 wg0 = ((const float4*)Wg)[lane];
    const float4 wg1 = ((const float4*)Wg)[lane + 32];
    const float bg0 = bg[0];
    const float p0  = p[0];

    const int beg = d_segstart[s];
    const int cnt = d_segstart[s + 1] - beg;

    float4 a0 = make_float4(0.f, 0.f, 0.f, 0.f);
    float4 a1 = make_float4(0.f, 0.f, 0.f, 0.f);
    float m = -INFINITY, den = 0.0f;

    float4 c0 = make_float4(0.f, 0.f, 0.f, 0.f);
    float4 c1 = make_float4(0.f, 0.f, 0.f, 0.f);
    float cw = 1.0f;
    if (cnt > 0) {
        size_t b = (size_t)beg * 64;
        c0 = x4[b + lane];
        c1 = x4[b + 32 + lane];
        cw = wts[beg];
    }

    for (int i = 0; i < cnt; i++) {
        float4 n0v = make_float4(0.f, 0.f, 0.f, 0.f);
        float4 n1v = make_float4(0.f, 0.f, 0.f, 0.f);
        float nw = 1.0f;
        if (i + 1 < cnt) {
            size_t b = (size_t)(beg + i + 1) * 64;
            n0v = x4[b + lane];
            n1v = x4[b + 32 + lane];
            nw = wts[beg + i + 1];
        }

        float dot = c0.x * wg0.x + c0.y * wg0.y + c0.z * wg0.z + c0.w * wg0.w
                  + c1.x * wg1.x + c1.y * wg1.y + c1.z * wg1.z + c1.w * wg1.w;
        #pragma unroll
        for (int o = 16; o; o >>= 1)
            dot += __shfl_xor_sync(0xffffffffu, dot, o);
        const float lg = dot + bg0;

        const float nm = fmaxf(m, lg);
        const float sc = ex2f((m - nm) * L2E);
        const float e  = ex2f(fmaf(p0, lg2f(cw), (lg - nm) * L2E));
        den = den * sc + e;
        a0.x = fmaf(e, c0.x, a0.x * sc);
        a0.y = fmaf(e, c0.y, a0.y * sc);
        a0.z = fmaf(e, c0.z, a0.z * sc);
        a0.w = fmaf(e, c0.w, a0.w * sc);
        a1.x = fmaf(e, c1.x, a1.x * sc);
        a1.y = fmaf(e, c1.y, a1.y * sc);
        a1.z = fmaf(e, c1.z, a1.z * sc);
        a1.w = fmaf(e, c1.w, a1.w * sc);
        m = nm;

        c0 = n0v; c1 = n1v; cw = nw;
    }

    const float inv = 1.0f / (den + 1e-10f);
    float4 r0, r1;
    r0.x = a0.x * inv; r0.y = a0.y * inv; r0.z = a0.z * inv; r0.w = a0.w * inv;
    r1.x = a1.x * inv; r1.y = a1.y * inv; r1.z = a1.z * inv; r1.w = a1.w * inv;

    {
        __nv_bfloat162 h01 = __floats2bfloat162_rn(r0.x, r0.y);
        __nv_bfloat162 h23 = __floats2bfloat162_rn(r0.z, r0.w);
        __nv_bfloat162 l01 = __floats2bfloat162_rn(r0.x - __bfloat162float(h01.x),
                                                   r0.y - __bfloat162float(h01.y));
        __nv_bfloat162 l23 = __floats2bfloat162_rn(r0.z - __bfloat162float(h23.x),
                                                   r0.w - __bfloat162float(h23.y));
        size_t o = (size_t)s * 256 + 4 * lane;
        uint2 uh, ul;
        memcpy(&uh.x, &h01, 4); memcpy(&uh.y, &h23, 4);
        memcpy(&ul.x, &l01, 4); memcpy(&ul.y, &l23, 4);
        *(uint2*)&d_ph[o] = uh;
        *(uint2*)&d_pl[o] = ul;
    }
    {
        __nv_bfloat162 h01 = __floats2bfloat162_rn(r1.x, r1.y);
        __nv_bfloat162 h23 = __floats2bfloat162_rn(r1.z, r1.w);
        __nv_bfloat162 l01 = __floats2bfloat162_rn(r1.x - __bfloat162float(h01.x),
                                                   r1.y - __bfloat162float(h01.y));
        __nv_bfloat162 l23 = __floats2bfloat162_rn(r1.z - __bfloat162float(h23.x),
                                                   r1.w - __bfloat162float(h23.y));
        size_t o = (size_t)s * 256 + 128 + 4 * lane;
        uint2 uh, ul;
        memcpy(&uh.x, &h01, 4); memcpy(&uh.y, &h23, 4);
        memcpy(&ul.x, &l01, 4); memcpy(&ul.y, &l23, 4);
        *(uint2*)&d_ph[o] = uh;
        *(uint2*)&d_pl[o] = ul;
    }
    if (lane == 0) d_gsum[s] = den * inv;
}

// ---------------------------------------------------------------------------
// Kernel 4: split-bf16 HMMA GEMM.
// CTA 64x128, 256 thr (warp grid 2Mx4N, warp tile 32x32), K-step 32,
// cp.async double buffer, 3 CTAs/SM. Intensity: 24 MMA per 8 LDSM.x4.
// ---------------------------------------------------------------------------
#define GM 64
#define GN 128
#define AK 40                       // bf16 per padded smem row (32 + 8)
#define A_TILE (64 * AK * 2)        // 5120 B  (per hi or lo)
#define B_TILE (128 * AK * 2)       // 10240 B
#define STAGE  (2 * A_TILE + 2 * B_TILE)   // 30720 B
// within a stage: Ah @0, Al @A_TILE, Bh @2*A_TILE, Bl @2*A_TILE+B_TILE

#define MMA_BF16(d, a, b)                                                     \
    asm volatile(                                                             \
        "mma.sync.aligned.m16n8k16.row.col.f32.bf16.bf16.f32 "                \
        "{%0,%1,%2,%3}, {%4,%5,%6,%7}, {%8,%9}, {%0,%1,%2,%3};"               \
        : "+f"((d)[0]), "+f"((d)[1]), "+f"((d)[2]), "+f"((d)[3])              \
        : "r"((a)[0]), "r"((a)[1]), "r"((a)[2]), "r"((a)[3]),                 \
          "r"((b)[0]), "r"((b)[1]))

__device__ __forceinline__ void ldsm_x4(unsigned& r0, unsigned& r1,
                                        unsigned& r2, unsigned& r3,
                                        unsigned addr) {
    asm volatile("ldmatrix.sync.aligned.m8n8.x4.shared.b16 {%0,%1,%2,%3}, [%4];"
                 : "=r"(r0), "=r"(r1), "=r"(r2), "=r"(r3) : "r"(addr));
}
__device__ __forceinline__ void cp16(unsigned dst, const void* src, int sz) {
    asm volatile("cp.async.cg.shared.global [%0], [%1], 16, %2;"
                 :: "r"(dst), "l"(src), "r"(sz));
}

__global__ __launch_bounds__(256, 3) void gemm_mma_kernel(
    const float* __restrict__ bm,
    float* __restrict__ out,
    int S)
{
    extern __shared__ char smem[];
    const unsigned sbase = (unsigned)__cvta_generic_to_shared(smem);

    const int tid  = threadIdx.x;
    const int warp = tid >> 5, lane = tid & 31;
    const int g = lane >> 2, t = lane & 3;
    const int wm = warp >> 2;          // 0..1 (M)
    const int wn = warp & 3;           // 0..3 (N)
    const int m0 = blockIdx.x * GM;
    const int n0 = blockIdx.y * GN;

    float acc[2][4][4] = {};           // [m16 tile][n8 frag][regs]

    // ---- loader mapping (256 threads) ----
    // A: row = tid>>2 (0..63), 16B chunk = tid&3; each thread 1 chunk Ah + Al.
    const int lrow = tid >> 2;
    const int lchk = tid & 3;
    int arow = m0 + lrow;
    const int asz = (arow < S) ? 16 : 0;
    if (arow >= S) arow = 0;
    const unsigned a_dst = (unsigned)(lrow * (AK * 2) + lchk * 16);
    // B: rows lrow and lrow+64, chunk lchk; hi + lo each -> 4 cp16/thread.
    const unsigned b_dst0 = (unsigned)(2 * A_TILE + lrow * (AK * 2) + lchk * 16);
    const unsigned b_dst1 = b_dst0 + (unsigned)(64 * (AK * 2));

    // ---- ldmatrix per-lane invariant offsets (bytes) ----
    unsigned a_off[2];
    #pragma unroll
    for (int i = 0; i < 2; i++)
        a_off[i] = (unsigned)((wm * 32 + i * 16 + (lane & 15)) * (AK * 2)
                              + (lane >> 4) * 16);
    unsigned b_off[2];
    #pragma unroll
    for (int j = 0; j < 2; j++)
        b_off[j] = (unsigned)((wn * 32 + j * 16 + ((lane >> 4) << 3) + (lane & 7))
                              * (AK * 2) + (((lane >> 3) & 1) << 4));

    auto load_stage = [&](int it) {
        const int kb = it * 32;
        const unsigned sb = sbase + (unsigned)((it & 1) * STAGE);
        const size_t ga  = (size_t)arow * 256 + kb + lchk * 8;
        const size_t gb0 = (size_t)(n0 + lrow) * 256 + kb + lchk * 8;
        const size_t gb1 = (size_t)(n0 + lrow + 64) * 256 + kb + lchk * 8;
        cp16(sb + a_dst,          &d_ph[ga], asz);
        cp16(sb + A_TILE + a_dst, &d_pl[ga], asz);
        cp16(sb + b_dst0,          &d_Wth[gb0], 16);
        cp16(sb + b_dst1,          &d_Wth[gb1], 16);
        cp16(sb + B_TILE + b_dst0, &d_Wtl[gb0], 16);
        cp16(sb + B_TILE + b_dst1, &d_Wtl[gb1], 16);
        asm volatile("cp.async.commit_group;");
    };

    load_stage(0);
    load_stage(1);

    #pragma unroll
    for (int it = 0; it < 8; it++) {
        if (it < 6) asm volatile("cp.async.wait_group 1;");
        else        asm volatile("cp.async.wait_group 0;");
        __syncthreads();

        const unsigned sb = sbase + (unsigned)((it & 1) * STAGE);

        #pragma unroll
        for (int kk = 0; kk < 2; kk++) {
            const unsigned kadd = kk * 32;   // 16 bf16 = 32 bytes

            unsigned ah[2][4], al[2][4];
            #pragma unroll
            for (int i = 0; i < 2; i++) {
                ldsm_x4(ah[i][0], ah[i][1], ah[i][2], ah[i][3],
                        sb + a_off[i] + kadd);
                ldsm_x4(al[i][0], al[i][1], al[i][2], al[i][3],
                        sb + A_TILE + a_off[i] + kadd);
            }
            unsigned bh[4][2], bl[4][2];
            #pragma unroll
            for (int j = 0; j < 2; j++) {
                unsigned r0, r1, r2, r3;
                ldsm_x4(r0, r1, r2, r3, sb + 2 * A_TILE + b_off[j] + kadd);
                bh[2 * j][0] = r0; bh[2 * j][1] = r1;
                bh[2 * j + 1][0] = r2; bh[2 * j + 1][1] = r3;
                ldsm_x4(r0, r1, r2, r3, sb + 2 * A_TILE + B_TILE + b_off[j] + kadd);
                bl[2 * j][0] = r0; bl[2 * j][1] = r1;
                bl[2 * j + 1][0] = r2; bl[2 * j + 1][1] = r3;
            }

            #pragma unroll
            for (int i = 0; i < 2; i++)
                #pragma unroll
                for (int j = 0; j < 4; j++) {
                    MMA_BF16(acc[i][j], ah[i], bh[j]);
                    MMA_BF16(acc[i][j], ah[i], bl[j]);
                    MMA_BF16(acc[i][j], al[i], bh[j]);
                }
        }
        __syncthreads();
        if (it + 2 < 8) load_stage(it + 2);
    }

    // ---- epilogue: + gsum[m] * bm[n] ----
    #pragma unroll
    for (int i = 0; i < 2; i++) {
        #pragma unroll
        for (int rr = 0; rr < 2; rr++) {
            const int mrow = m0 + wm * 32 + i * 16 + g + rr * 8;
            if (mrow < S) {
                const float gs = d_gsum[mrow];
                #pragma unroll
                for (int j = 0; j < 4; j++) {
                    const int n = n0 + wn * 32 + j * 8 + 2 * t;
                    float2 o;
                    o.x = acc[i][j][rr * 2 + 0] + gs * bm[n];
                    o.y = acc[i][j][rr * 2 + 1] + gs * bm[n + 1];
                    *(float2*)&out[(size_t)mrow * 256 + n] = o;
                }
            }
        }
    }
}

// ---------------------------------------------------------------------------
// Inputs: x, weights, Wg, bg, Wm, bm, p, index, num_segments
// ---------------------------------------------------------------------------
extern "C" void kernel_launch(void* const* d_in, const int* in_sizes, int n_in,
                              void* d_out, int out_size) {
    const float* x     = (const float*)d_in[0];
    const float* wts   = (const float*)d_in[1];
    const float* Wg    = (const float*)d_in[2];
    const float* bg    = (const float*)d_in[3];
    const float* Wm    = (const float*)d_in[4];
    const float* bm    = (const float*)d_in[5];
    const float* p     = (const float*)d_in[6];
    const int*   index = (const int*)d_in[7];

    const int N = in_sizes[7];
    const int S = out_size / 256;
    const int smem_bytes = 2 * STAGE;   // 61440

    cudaFuncSetAttribute(gemm_mma_kernel,
                         cudaFuncAttributeMaxDynamicSharedMemorySize, smem_bytes);

    seg_bounds_kernel<<<(N / 4 + 256) / 256, 256>>>(index, N, S);
    prep_kernel<<<dim3(8, 8), dim3(32, 8)>>>(Wm);
    pool_kernel<<<(S + 7) / 8, 256>>>(x, wts, Wg, bg, p, S);
    gemm_mma_kernel<<<dim3((S + GM - 1) / GM, 256 / GN), 256, smem_bytes>>>(
        bm, (float*)d_out, S);
}

// round 10
// speedup vs baseline: 1.1572x; 1.1572x over previous
#include <cuda_runtime.h>
#include <cuda_bf16.h>
#include <cstdint>
#include <cstring>
#include <math.h>

#define MAXS 24576

__device__ int   d_segstart[MAXS + 1];
__device__ float d_gsum[MAXS];
__device__ __nv_bfloat16 d_ph[(size_t)MAXS * 256];   // pooled hi (bf16 split)
__device__ __nv_bfloat16 d_pl[(size_t)MAXS * 256];   // pooled lo
__device__ __nv_bfloat16 d_Wth[256 * 256];           // Wm^T hi  [n][k]
__device__ __nv_bfloat16 d_Wtl[256 * 256];           // Wm^T lo

__device__ __forceinline__ float ex2f(float x) {
    float y; asm("ex2.approx.ftz.f32 %0, %1;" : "=f"(y) : "f"(x)); return y;
}
__device__ __forceinline__ float lg2f(float x) {
    float y; asm("lg2.approx.ftz.f32 %0, %1;" : "=f"(y) : "f"(x)); return y;
}
#define L2E 1.4426950408889634f

// ---------------------------------------------------------------------------
// Kernel 1: segment boundaries (index sorted), 4 nodes per thread.
// ---------------------------------------------------------------------------
__global__ void seg_bounds_kernel(const int* __restrict__ index, int N, int S) {
    int base = (blockIdx.x * blockDim.x + threadIdx.x) * 4;
    if (base >= N) return;
    int prev = (base == 0) ? -1 : index[base - 1];
    int v[4];
    if (base + 3 < N) {
        int4 q = *(const int4*)&index[base];
        v[0] = q.x; v[1] = q.y; v[2] = q.z; v[3] = q.w;
    } else {
        for (int k = 0; k < 4; k++) v[k] = (base + k < N) ? index[base + k] : 0;
    }
    #pragma unroll
    for (int k = 0; k < 4; k++) {
        int n = base + k;
        if (n < N) {
            for (int s = prev + 1; s <= v[k]; s++) d_segstart[s] = n;
            prev = v[k];
            if (n == N - 1)
                for (int s = v[k] + 1; s <= S; s++) d_segstart[s] = N;
        }
    }
}

// ---------------------------------------------------------------------------
// Kernel 2: pooling (one warp per segment, online softmax, depth-2 prefetch)
// + fused Wm prep (last 64 blocks transpose+split Wm — independent work).
// ---------------------------------------------------------------------------
__global__ __launch_bounds__(256) void pool_kernel(
    const float* __restrict__ x,
    const float* __restrict__ wts,
    const float* __restrict__ Wg,
    const float* __restrict__ bg,
    const float* __restrict__ p,
    const float* __restrict__ Wm,
    int S, int poolBlocks)
{
    // ---- fused prep branch ----
    if ((int)blockIdx.x >= poolBlocks) {
        __shared__ float tile[32][33];
        const int id = blockIdx.x - poolBlocks;     // 0..63
        const int n0 = (id & 7) * 32, k0 = (id >> 3) * 32;
        const int tx = threadIdx.x & 31, ty = threadIdx.x >> 5;
        for (int r = ty; r < 32; r += 8)
            tile[r][tx] = Wm[(size_t)(k0 + r) * 256 + n0 + tx];
        __syncthreads();
        for (int r = ty; r < 32; r += 8) {
            float v = tile[tx][r];
            __nv_bfloat16 h = __float2bfloat16(v);
            __nv_bfloat16 l = __float2bfloat16(v - __bfloat162float(h));
            size_t o = (size_t)(n0 + r) * 256 + k0 + tx;
            d_Wth[o] = h;
            d_Wtl[o] = l;
        }
        return;
    }

    const int s = blockIdx.x * 8 + (threadIdx.x >> 5);
    if (s >= S) return;
    const int lane = threadIdx.x & 31;

    const float4* __restrict__ x4 = (const float4*)x;
    const float4 wg0 = ((const float4*)Wg)[lane];
    const float4 wg1 = ((const float4*)Wg)[lane + 32];
    const float bg0 = bg[0];
    const float p0  = p[0];

    const int beg = d_segstart[s];
    const int cnt = d_segstart[s + 1] - beg;

    float4 a0 = make_float4(0.f, 0.f, 0.f, 0.f);
    float4 a1 = make_float4(0.f, 0.f, 0.f, 0.f);
    float m = -INFINITY, den = 0.0f;

    // depth-2 prefetch ring: c = current, d = next
    float4 c0 = make_float4(0.f, 0.f, 0.f, 0.f), c1 = c0, d0 = c0, d1 = c0;
    float cw = 1.0f, dw = 1.0f;
    if (cnt > 0) {
        size_t b = (size_t)beg * 64;
        c0 = x4[b + lane];
        c1 = x4[b + 32 + lane];
        cw = wts[beg];
    }
    if (cnt > 1) {
        size_t b = (size_t)(beg + 1) * 64;
        d0 = x4[b + lane];
        d1 = x4[b + 32 + lane];
        dw = wts[beg + 1];
    }

    for (int i = 0; i < cnt; i++) {
        float4 e0 = make_float4(0.f, 0.f, 0.f, 0.f), e1 = e0;
        float ew = 1.0f;
        if (i + 2 < cnt) {
            size_t b = (size_t)(beg + i + 2) * 64;
            e0 = x4[b + lane];
            e1 = x4[b + 32 + lane];
            ew = wts[beg + i + 2];
        }

        float dot = c0.x * wg0.x + c0.y * wg0.y + c0.z * wg0.z + c0.w * wg0.w
                  + c1.x * wg1.x + c1.y * wg1.y + c1.z * wg1.z + c1.w * wg1.w;
        #pragma unroll
        for (int o = 16; o; o >>= 1)
            dot += __shfl_xor_sync(0xffffffffu, dot, o);
        const float lg = dot + bg0;

        const float nm = fmaxf(m, lg);
        const float sc = ex2f((m - nm) * L2E);
        const float e  = ex2f(fmaf(p0, lg2f(cw), (lg - nm) * L2E));
        den = den * sc + e;
        a0.x = fmaf(e, c0.x, a0.x * sc);
        a0.y = fmaf(e, c0.y, a0.y * sc);
        a0.z = fmaf(e, c0.z, a0.z * sc);
        a0.w = fmaf(e, c0.w, a0.w * sc);
        a1.x = fmaf(e, c1.x, a1.x * sc);
        a1.y = fmaf(e, c1.y, a1.y * sc);
        a1.z = fmaf(e, c1.z, a1.z * sc);
        a1.w = fmaf(e, c1.w, a1.w * sc);
        m = nm;

        c0 = d0; c1 = d1; cw = dw;
        d0 = e0; d1 = e1; dw = ew;
    }

    const float inv = 1.0f / (den + 1e-10f);
    float4 r0, r1;
    r0.x = a0.x * inv; r0.y = a0.y * inv; r0.z = a0.z * inv; r0.w = a0.w * inv;
    r1.x = a1.x * inv; r1.y = a1.y * inv; r1.z = a1.z * inv; r1.w = a1.w * inv;

    {
        __nv_bfloat162 h01 = __floats2bfloat162_rn(r0.x, r0.y);
        __nv_bfloat162 h23 = __floats2bfloat162_rn(r0.z, r0.w);
        __nv_bfloat162 l01 = __floats2bfloat162_rn(r0.x - __bfloat162float(h01.x),
                                                   r0.y - __bfloat162float(h01.y));
        __nv_bfloat162 l23 = __floats2bfloat162_rn(r0.z - __bfloat162float(h23.x),
                                                   r0.w - __bfloat162float(h23.y));
        size_t o = (size_t)s * 256 + 4 * lane;
        uint2 uh, ul;
        memcpy(&uh.x, &h01, 4); memcpy(&uh.y, &h23, 4);
        memcpy(&ul.x, &l01, 4); memcpy(&ul.y, &l23, 4);
        *(uint2*)&d_ph[o] = uh;
        *(uint2*)&d_pl[o] = ul;
    }
    {
        __nv_bfloat162 h01 = __floats2bfloat162_rn(r1.x, r1.y);
        __nv_bfloat162 h23 = __floats2bfloat162_rn(r1.z, r1.w);
        __nv_bfloat162 l01 = __floats2bfloat162_rn(r1.x - __bfloat162float(h01.x),
                                                   r1.y - __bfloat162float(h01.y));
        __nv_bfloat162 l23 = __floats2bfloat162_rn(r1.z - __bfloat162float(h23.x),
                                                   r1.w - __bfloat162float(h23.y));
        size_t o = (size_t)s * 256 + 128 + 4 * lane;
        uint2 uh, ul;
        memcpy(&uh.x, &h01, 4); memcpy(&uh.y, &h23, 4);
        memcpy(&ul.x, &l01, 4); memcpy(&ul.y, &l23, 4);
        *(uint2*)&d_ph[o] = uh;
        *(uint2*)&d_pl[o] = ul;
    }
    if (lane == 0) d_gsum[s] = den * inv;
}

// ---------------------------------------------------------------------------
// Kernel 3: split-bf16 HMMA GEMM (R8 config + 3-stage cp.async pipeline).
// Block tile 128x64 (512 thr, 4x4 warp grid, warp tile 32x16), K-step 32,
// 2 CTAs/SM.
// ---------------------------------------------------------------------------
#define GM 128
#define GN 64
#define AK 40                       // bf16 per padded smem row (32 + 8)
#define A_TILE (128 * AK * 2)       // 10240 B
#define B_TILE (64 * AK * 2)        // 5120 B
#define STAGE  (2 * A_TILE + 2 * B_TILE)   // 30720 B
#define NSTAGE 3
// within a stage: Ah @0, Al @A_TILE, Bh @2*A_TILE, Bl @2*A_TILE+B_TILE

#define MMA_BF16(d, a, b)                                                     \
    asm volatile(                                                             \
        "mma.sync.aligned.m16n8k16.row.col.f32.bf16.bf16.f32 "                \
        "{%0,%1,%2,%3}, {%4,%5,%6,%7}, {%8,%9}, {%0,%1,%2,%3};"               \
        : "+f"((d)[0]), "+f"((d)[1]), "+f"((d)[2]), "+f"((d)[3])              \
        : "r"((a)[0]), "r"((a)[1]), "r"((a)[2]), "r"((a)[3]),                 \
          "r"((b)[0]), "r"((b)[1]))

__device__ __forceinline__ void ldsm_x4(unsigned& r0, unsigned& r1,
                                        unsigned& r2, unsigned& r3,
                                        unsigned addr) {
    asm volatile("ldmatrix.sync.aligned.m8n8.x4.shared.b16 {%0,%1,%2,%3}, [%4];"
                 : "=r"(r0), "=r"(r1), "=r"(r2), "=r"(r3) : "r"(addr));
}
__device__ __forceinline__ void cp16(unsigned dst, const void* src, int sz) {
    asm volatile("cp.async.cg.shared.global [%0], [%1], 16, %2;"
                 :: "r"(dst), "l"(src), "r"(sz));
}

__global__ __launch_bounds__(512, 2) void gemm_mma_kernel(
    const float* __restrict__ bm,
    float* __restrict__ out,
    int S)
{
    extern __shared__ char smem[];
    const unsigned sbase = (unsigned)__cvta_generic_to_shared(smem);

    const int tid  = threadIdx.x;
    const int warp = tid >> 5, lane = tid & 31;
    const int g = lane >> 2, t = lane & 3;
    const int wm = warp >> 2;          // 0..3 (M)
    const int wn = warp & 3;           // 0..3 (N)
    const int m0 = blockIdx.x * GM;
    const int n0 = blockIdx.y * GN;

    float acc[2][2][4] = {};           // [m16 tile][n8 frag][regs]

    // ---- loader mapping ----
    const int lrow = tid >> 2;         // 0..127
    const int lchk = tid & 3;          // 0..3
    int arow = m0 + lrow;
    const int asz = (arow < S) ? 16 : 0;
    if (arow >= S) arow = 0;
    const unsigned a_dst = (unsigned)(lrow * (AK * 2) + lchk * 16);
    const int b_hl  = tid >> 8;
    const int b_row = (tid & 255) >> 2;
    const int b_chk = tid & 3;
    const unsigned b_dst = (unsigned)(2 * A_TILE + b_hl * B_TILE
                                      + b_row * (AK * 2) + b_chk * 16);
    const __nv_bfloat16* __restrict__ bsrc = b_hl ? d_Wtl : d_Wth;

    // ---- ldmatrix per-lane invariant offsets (bytes) ----
    unsigned a_off[2];
    #pragma unroll
    for (int i = 0; i < 2; i++)
        a_off[i] = (unsigned)((wm * 32 + i * 16 + (lane & 15)) * (AK * 2)
                              + (lane >> 4) * 16);
    const unsigned b_off =
        (unsigned)((wn * 16 + ((lane >> 4) << 3) + (lane & 7)) * (AK * 2)
                   + (((lane >> 3) & 1) << 4));

    auto load_stage = [&](int it) {
        const int kb = it * 32;
        const unsigned sb = sbase + (unsigned)((it % NSTAGE) * STAGE);
        cp16(sb + a_dst,          &d_ph[(size_t)arow * 256 + kb + lchk * 8], asz);
        cp16(sb + A_TILE + a_dst, &d_pl[(size_t)arow * 256 + kb + lchk * 8], asz);
        cp16(sb + b_dst, &bsrc[(size_t)(n0 + b_row) * 256 + kb + b_chk * 8], 16);
        asm volatile("cp.async.commit_group;");
    };

    load_stage(0);
    load_stage(1);
    load_stage(2);

    #pragma unroll
    for (int it = 0; it < 8; it++) {
        if (it < 6)      asm volatile("cp.async.wait_group 2;");
        else if (it == 6) asm volatile("cp.async.wait_group 1;");
        else              asm volatile("cp.async.wait_group 0;");
        __syncthreads();

        const unsigned sb = sbase + (unsigned)((it % NSTAGE) * STAGE);

        #pragma unroll
        for (int kk = 0; kk < 2; kk++) {
            const unsigned kadd = kk * 32;   // 16 bf16 = 32 bytes

            unsigned ah[2][4], al[2][4];
            #pragma unroll
            for (int i = 0; i < 2; i++) {
                ldsm_x4(ah[i][0], ah[i][1], ah[i][2], ah[i][3],
                        sb + a_off[i] + kadd);
                ldsm_x4(al[i][0], al[i][1], al[i][2], al[i][3],
                        sb + A_TILE + a_off[i] + kadd);
            }
            unsigned bh[2][2], bl[2][2];
            {
                unsigned r0, r1, r2, r3;
                ldsm_x4(r0, r1, r2, r3, sb + 2 * A_TILE + b_off + kadd);
                bh[0][0] = r0; bh[0][1] = r1; bh[1][0] = r2; bh[1][1] = r3;
                ldsm_x4(r0, r1, r2, r3, sb + 2 * A_TILE + B_TILE + b_off + kadd);
                bl[0][0] = r0; bl[0][1] = r1; bl[1][0] = r2; bl[1][1] = r3;
            }

            #pragma unroll
            for (int i = 0; i < 2; i++)
                #pragma unroll
                for (int j = 0; j < 2; j++) {
                    MMA_BF16(acc[i][j], ah[i], bh[j]);
                    MMA_BF16(acc[i][j], ah[i], bl[j]);
                    MMA_BF16(acc[i][j], al[i], bh[j]);
                }
        }
        __syncthreads();
        if (it + NSTAGE < 8) load_stage(it + NSTAGE);
    }

    // ---- epilogue: + gsum[m] * bm[n] ----
    #pragma unroll
    for (int i = 0; i < 2; i++) {
        #pragma unroll
        for (int rr = 0; rr < 2; rr++) {
            const int mrow = m0 + wm * 32 + i * 16 + g + rr * 8;
            if (mrow < S) {
                const float gs = d_gsum[mrow];
                #pragma unroll
                for (int j = 0; j < 2; j++) {
                    const int n = n0 + wn * 16 + j * 8 + 2 * t;
                    float2 o;
                    o.x = acc[i][j][rr * 2 + 0] + gs * bm[n];
                    o.y = acc[i][j][rr * 2 + 1] + gs * bm[n + 1];
                    *(float2*)&out[(size_t)mrow * 256 + n] = o;
                }
            }
        }
    }
}

// ---------------------------------------------------------------------------
// Inputs: x, weights, Wg, bg, Wm, bm, p, index, num_segments
// ---------------------------------------------------------------------------
extern "C" void kernel_launch(void* const* d_in, const int* in_sizes, int n_in,
                              void* d_out, int out_size) {
    const float* x     = (const float*)d_in[0];
    const float* wts   = (const float*)d_in[1];
    const float* Wg    = (const float*)d_in[2];
    const float* bg    = (const float*)d_in[3];
    const float* Wm    = (const float*)d_in[4];
    const float* bm    = (const float*)d_in[5];
    const float* p     = (const float*)d_in[6];
    const int*   index = (const int*)d_in[7];

    const int N = in_sizes[7];
    const int S = out_size / 256;
    const int smem_bytes = NSTAGE * STAGE;   // 92160

    cudaFuncSetAttribute(gemm_mma_kernel,
                         cudaFuncAttributeMaxDynamicSharedMemorySize, smem_bytes);

    const int poolBlocks = (S + 7) / 8;

    seg_bounds_kernel<<<(N / 4 + 256) / 256, 256>>>(index, N, S);
    pool_kernel<<<poolBlocks + 64, 256>>>(x, wts, Wg, bg, p, Wm, S, poolBlocks);
    gemm_mma_kernel<<<dim3((S + GM - 1) / GM, 256 / GN), 512, smem_bytes>>>(
        bm, (float*)d_out, S);
}